// round 8
// baseline (speedup 1.0000x reference)
#include <cuda_runtime.h>
#include <cuda_bf16.h>

// ---------------------------------------------------------------------------
// GCN 3-layer. Per layer: support = H @ W ; agg[n] = sum_{e:dst=n} support[src_e]*val_e + b
// SpMM is GATHER-based: edges bucketed by dst once per call into packed
// (src, val) int2 slots; each node's group accumulates in-edges in registers
// with x4-unrolled independent gathers (MLP=4) and writes once.
// ReLU fused into next GEMM's A-load.
// ---------------------------------------------------------------------------

#define MAX_NODES 100000
#define SLOTS 64   // max in-degree capacity; deg ~ Poisson(10), P(>=64) ~ 1e-30

static __device__ float g_sup[(size_t)MAX_NODES * 64];
static __device__ float g_hA[(size_t)MAX_NODES * 64];
static __device__ float g_hB[(size_t)MAX_NODES * 64];

static __device__ int  g_cnt[MAX_NODES];
static __device__ int2 g_bpair[(size_t)MAX_NODES * SLOTS];   // (src, val bits)

// ---------------------------------------------------------------------------
// Bucket build: zero counters, then slot edges by dst (packed pair store).
// ---------------------------------------------------------------------------
__global__ void zero_cnt_kernel(int n) {
    int i = blockIdx.x * blockDim.x + threadIdx.x;
    if (i < n) g_cnt[i] = 0;
}

__global__ void bucket_build_kernel(const int* __restrict__ src,
                                    const int* __restrict__ dst,
                                    const float* __restrict__ val, int E) {
    int e = blockIdx.x * blockDim.x + threadIdx.x;
    if (e >= E) return;
    int d = __ldg(dst + e);
    int slot = atomicAdd(&g_cnt[d], 1);
    if (slot < SLOTS)
        g_bpair[(size_t)d * SLOTS + slot] =
            make_int2(__ldg(src + e), __float_as_int(__ldg(val + e)));
}

// ---------------------------------------------------------------------------
// Gather SpMM + bias:  out[n, :] = bias + sum_s sup[src_s, :] * val_s
// Group of G = D/2 threads per node, float2 of features per thread.
// x4 unroll, two accumulators -> 4 independent row-gathers in flight.
// ---------------------------------------------------------------------------
template <int D>
__global__ void __launch_bounds__(256) gather_spmm_kernel(
    const float* __restrict__ sup, const float* __restrict__ bias,
    float* __restrict__ outp, int M) {
    constexpr int G = D / 2;
    int t = blockIdx.x * blockDim.x + threadIdx.x;
    int n = t / G;
    int lane = t % G;
    if (n >= M) return;

    int cnt = min(g_cnt[n], SLOTS);
    const int2* bp = g_bpair + (size_t)n * SLOTS;

    float2 acc0, acc1;
    acc0.x = __ldg(bias + lane * 2);
    acc0.y = __ldg(bias + lane * 2 + 1);
    acc1.x = 0.f; acc1.y = 0.f;

    int s = 0;
    for (; s + 4 <= cnt; s += 4) {
        int2 p0 = __ldg(bp + s);
        int2 p1 = __ldg(bp + s + 1);
        int2 p2 = __ldg(bp + s + 2);
        int2 p3 = __ldg(bp + s + 3);
        float2 m0 = *reinterpret_cast<const float2*>(sup + (size_t)p0.x * D + lane * 2);
        float2 m1 = *reinterpret_cast<const float2*>(sup + (size_t)p1.x * D + lane * 2);
        float2 m2 = *reinterpret_cast<const float2*>(sup + (size_t)p2.x * D + lane * 2);
        float2 m3 = *reinterpret_cast<const float2*>(sup + (size_t)p3.x * D + lane * 2);
        float v0 = __int_as_float(p0.y), v1 = __int_as_float(p1.y);
        float v2 = __int_as_float(p2.y), v3 = __int_as_float(p3.y);
        acc0.x += m0.x * v0; acc0.y += m0.y * v0;
        acc1.x += m1.x * v1; acc1.y += m1.y * v1;
        acc0.x += m2.x * v2; acc0.y += m2.y * v2;
        acc1.x += m3.x * v3; acc1.y += m3.y * v3;
    }
    for (; s < cnt; s++) {
        int2 p = __ldg(bp + s);
        float v = __int_as_float(p.y);
        float2 m = *reinterpret_cast<const float2*>(sup + (size_t)p.x * D + lane * 2);
        acc0.x += m.x * v; acc0.y += m.y * v;
    }
    acc0.x += acc1.x; acc0.y += acc1.y;
    *reinterpret_cast<float2*>(outp + (size_t)n * D + lane * 2) = acc0;
}

// ---------------------------------------------------------------------------
// GEMM: C[M,NO] = (RELU? relu(A) : A)[M,K] @ W[K,NO]
// 256 threads, BM=128, register tile TM x 4 per thread.
// ---------------------------------------------------------------------------
template <int K, int NO, bool RELU>
__global__ void __launch_bounds__(256) gemm_kernel(
    const float* __restrict__ A, const float* __restrict__ W,
    float* __restrict__ C, int M) {
    constexpr int BM = 128, BK = 32;
    constexpr int TX = NO / 4;       // threads across columns (float4 each)
    constexpr int TY = 256 / TX;     // thread rows
    constexpr int TM = BM / TY;      // rows per thread

    __shared__ float  Asm[BM][BK + 1];
    __shared__ float4 Wsm[BK][NO / 4];

    const int tid = threadIdx.x;
    const int tx = tid % TX;
    const int ty = tid / TX;
    const int row0 = blockIdx.x * BM;

    float4 acc[TM];
    #pragma unroll
    for (int i = 0; i < TM; i++) acc[i] = make_float4(0.f, 0.f, 0.f, 0.f);

    const float4* W4 = reinterpret_cast<const float4*>(W);

    for (int kc = 0; kc < K; kc += BK) {
        __syncthreads();
        #pragma unroll
        for (int i = tid; i < BK * (NO / 4); i += 256) {
            int kk = i / (NO / 4), j = i % (NO / 4);
            Wsm[kk][j] = W4[(size_t)(kc + kk) * (NO / 4) + j];
        }
        #pragma unroll
        for (int i = 0; i < BM * BK / 256; i++) {
            int idx = i * 256 + tid;
            int r = idx / BK, kk = idx % BK;
            int gr = row0 + r;
            float a = (gr < M) ? A[(size_t)gr * K + kc + kk] : 0.f;
            if (RELU) a = fmaxf(a, 0.f);
            Asm[r][kk] = a;
        }
        __syncthreads();

        #pragma unroll
        for (int kk = 0; kk < BK; kk++) {
            float4 w = Wsm[kk][tx];
            #pragma unroll
            for (int i = 0; i < TM; i++) {
                float a = Asm[ty * TM + i][kk];
                acc[i].x += a * w.x;
                acc[i].y += a * w.y;
                acc[i].z += a * w.z;
                acc[i].w += a * w.w;
            }
        }
    }

    #pragma unroll
    for (int i = 0; i < TM; i++) {
        int r = row0 + ty * TM + i;
        if (r < M)
            *reinterpret_cast<float4*>(C + (size_t)r * NO + tx * 4) = acc[i];
    }
}

// ---------------------------------------------------------------------------
// Launch
// ---------------------------------------------------------------------------
extern "C" void kernel_launch(void* const* d_in, const int* in_sizes, int n_in,
                              void* d_out, int out_size) {
    const float* x        = (const float*)d_in[0];
    const float* edge_val = (const float*)d_in[1];
    const float* W1       = (const float*)d_in[2];
    const float* b1       = (const float*)d_in[3];
    const float* W2       = (const float*)d_in[4];
    const float* b2       = (const float*)d_in[5];
    const float* W3       = (const float*)d_in[6];
    const float* b3       = (const float*)d_in[7];
    const int*   esrc     = (const int*)d_in[8];
    const int*   edst     = (const int*)d_in[9];
    float* out = (float*)d_out;

    const int N = in_sizes[0] / 128;
    const int E = in_sizes[8];

    float *sup, *hA, *hB;
    cudaGetSymbolAddress((void**)&sup, g_sup);
    cudaGetSymbolAddress((void**)&hA, g_hA);
    cudaGetSymbolAddress((void**)&hB, g_hB);

    const int gemm_blocks = (N + 127) / 128;
    const int g64_blocks  = (N * 32 + 255) / 256;   // G=32 threads/node
    const int g16_blocks  = (N * 8 + 255) / 256;    // G=8 threads/node

    // Build dst-buckets once; reused by all three SpMM gathers.
    zero_cnt_kernel<<<(N + 255) / 256, 256>>>(N);
    bucket_build_kernel<<<(E + 255) / 256, 256>>>(esrc, edst, edge_val, E);

    // Layer 1: sup = x@W1 ; hA = gather(sup) + b1
    gemm_kernel<128, 64, false><<<gemm_blocks, 256>>>(x, W1, sup, N);
    gather_spmm_kernel<64><<<g64_blocks, 256>>>(sup, b1, hA, N);

    // Layer 2: sup = relu(hA)@W2 ; hB = gather(sup) + b2
    gemm_kernel<64, 64, true><<<gemm_blocks, 256>>>(hA, W2, sup, N);
    gather_spmm_kernel<64><<<g64_blocks, 256>>>(sup, b2, hB, N);

    // Layer 3: sup = relu(hB)@W3 ; out = gather(sup) + b3
    gemm_kernel<64, 16, true><<<gemm_blocks, 256>>>(hB, W3, sup, N);
    gather_spmm_kernel<16><<<g16_blocks, 256>>>(sup, b3, out, N);
}

// round 9
// speedup vs baseline: 1.0629x; 1.0629x over previous
#include <cuda_runtime.h>
#include <cuda_bf16.h>

// ---------------------------------------------------------------------------
// GCN 3-layer. Per layer: support = H @ W ; agg[n] = sum_{e:dst=n} support[src_e]*val_e + b
// SpMM is GATHER-based: edges bucketed by dst (packed (src,val) int2 slots),
// buckets PADDED to a multiple of 4 with (0, 0.0f) no-op edges so the gather
// loop is pure MLP=4 with no serial tail. ReLU fused into next GEMM's A-load.
// ---------------------------------------------------------------------------

#define MAX_NODES 100000
#define SLOTS 64   // max in-degree capacity; deg ~ Poisson(10), P(>=64) ~ 1e-30

static __device__ float g_sup[(size_t)MAX_NODES * 64];
static __device__ float g_hA[(size_t)MAX_NODES * 64];
static __device__ float g_hB[(size_t)MAX_NODES * 64];

static __device__ int  g_cnt[MAX_NODES];
static __device__ int2 g_bpair[(size_t)MAX_NODES * SLOTS];   // (src, val bits)

// ---------------------------------------------------------------------------
// Bucket build: zero counters, slot edges by dst, then pad to multiple of 4.
// ---------------------------------------------------------------------------
__global__ void zero_cnt_kernel(int n) {
    int i = blockIdx.x * blockDim.x + threadIdx.x;
    if (i < n) g_cnt[i] = 0;
}

__global__ void bucket_build_kernel(const int* __restrict__ src,
                                    const int* __restrict__ dst,
                                    const float* __restrict__ val, int E) {
    int e = blockIdx.x * blockDim.x + threadIdx.x;
    if (e >= E) return;
    int d = __ldg(dst + e);
    int slot = atomicAdd(&g_cnt[d], 1);
    if (slot < SLOTS)
        g_bpair[(size_t)d * SLOTS + slot] =
            make_int2(__ldg(src + e), __float_as_int(__ldg(val + e)));
}

// Pad each bucket with (src=0, val=0) no-op edges up to a multiple of 4, and
// store the padded count. 0 * sup[0] contributes exactly nothing.
__global__ void bucket_pad_kernel(int n) {
    int i = blockIdx.x * blockDim.x + threadIdx.x;
    if (i >= n) return;
    int c = min(g_cnt[i], SLOTS);
    int cp = min((c + 3) & ~3, SLOTS);
    int2* bp = g_bpair + (size_t)i * SLOTS;
    for (int s = c; s < cp; s++) bp[s] = make_int2(0, 0);
    g_cnt[i] = cp;
}

// ---------------------------------------------------------------------------
// Gather SpMM + bias:  out[n, :] = bias + sum_s sup[src_s, :] * val_s
// Group of G = D/2 threads per node, float2 of features per thread.
// cnt is a multiple of 4 -> single loop, 4 independent row-gathers in flight.
// ---------------------------------------------------------------------------
template <int D>
__global__ void __launch_bounds__(256) gather_spmm_kernel(
    const float* __restrict__ sup, const float* __restrict__ bias,
    float* __restrict__ outp, int M) {
    constexpr int G = D / 2;
    int t = blockIdx.x * blockDim.x + threadIdx.x;
    int n = t / G;
    int lane = t % G;
    if (n >= M) return;

    int cnt = g_cnt[n];                 // padded to multiple of 4, <= SLOTS
    const int2* bp = g_bpair + (size_t)n * SLOTS;

    float2 acc0, acc1;
    acc0.x = __ldg(bias + lane * 2);
    acc0.y = __ldg(bias + lane * 2 + 1);
    acc1.x = 0.f; acc1.y = 0.f;

    for (int s = 0; s < cnt; s += 4) {
        int2 p0 = __ldg(bp + s);
        int2 p1 = __ldg(bp + s + 1);
        int2 p2 = __ldg(bp + s + 2);
        int2 p3 = __ldg(bp + s + 3);
        float2 m0 = *reinterpret_cast<const float2*>(sup + (size_t)p0.x * D + lane * 2);
        float2 m1 = *reinterpret_cast<const float2*>(sup + (size_t)p1.x * D + lane * 2);
        float2 m2 = *reinterpret_cast<const float2*>(sup + (size_t)p2.x * D + lane * 2);
        float2 m3 = *reinterpret_cast<const float2*>(sup + (size_t)p3.x * D + lane * 2);
        float v0 = __int_as_float(p0.y), v1 = __int_as_float(p1.y);
        float v2 = __int_as_float(p2.y), v3 = __int_as_float(p3.y);
        acc0.x += m0.x * v0; acc0.y += m0.y * v0;
        acc1.x += m1.x * v1; acc1.y += m1.y * v1;
        acc0.x += m2.x * v2; acc0.y += m2.y * v2;
        acc1.x += m3.x * v3; acc1.y += m3.y * v3;
    }
    acc0.x += acc1.x; acc0.y += acc1.y;
    *reinterpret_cast<float2*>(outp + (size_t)n * D + lane * 2) = acc0;
}

// ---------------------------------------------------------------------------
// GEMM: C[M,NO] = (RELU? relu(A) : A)[M,K] @ W[K,NO]
// 256 threads, BM=128, register tile TM x 4 per thread.
// ---------------------------------------------------------------------------
template <int K, int NO, bool RELU>
__global__ void __launch_bounds__(256) gemm_kernel(
    const float* __restrict__ A, const float* __restrict__ W,
    float* __restrict__ C, int M) {
    constexpr int BM = 128, BK = 32;
    constexpr int TX = NO / 4;       // threads across columns (float4 each)
    constexpr int TY = 256 / TX;     // thread rows
    constexpr int TM = BM / TY;      // rows per thread

    __shared__ float  Asm[BM][BK + 1];
    __shared__ float4 Wsm[BK][NO / 4];

    const int tid = threadIdx.x;
    const int tx = tid % TX;
    const int ty = tid / TX;
    const int row0 = blockIdx.x * BM;

    float4 acc[TM];
    #pragma unroll
    for (int i = 0; i < TM; i++) acc[i] = make_float4(0.f, 0.f, 0.f, 0.f);

    const float4* W4 = reinterpret_cast<const float4*>(W);

    for (int kc = 0; kc < K; kc += BK) {
        __syncthreads();
        #pragma unroll
        for (int i = tid; i < BK * (NO / 4); i += 256) {
            int kk = i / (NO / 4), j = i % (NO / 4);
            Wsm[kk][j] = W4[(size_t)(kc + kk) * (NO / 4) + j];
        }
        #pragma unroll
        for (int i = 0; i < BM * BK / 256; i++) {
            int idx = i * 256 + tid;
            int r = idx / BK, kk = idx % BK;
            int gr = row0 + r;
            float a = (gr < M) ? A[(size_t)gr * K + kc + kk] : 0.f;
            if (RELU) a = fmaxf(a, 0.f);
            Asm[r][kk] = a;
        }
        __syncthreads();

        #pragma unroll
        for (int kk = 0; kk < BK; kk++) {
            float4 w = Wsm[kk][tx];
            #pragma unroll
            for (int i = 0; i < TM; i++) {
                float a = Asm[ty * TM + i][kk];
                acc[i].x += a * w.x;
                acc[i].y += a * w.y;
                acc[i].z += a * w.z;
                acc[i].w += a * w.w;
            }
        }
    }

    #pragma unroll
    for (int i = 0; i < TM; i++) {
        int r = row0 + ty * TM + i;
        if (r < M)
            *reinterpret_cast<float4*>(C + (size_t)r * NO + tx * 4) = acc[i];
    }
}

// ---------------------------------------------------------------------------
// Launch
// ---------------------------------------------------------------------------
extern "C" void kernel_launch(void* const* d_in, const int* in_sizes, int n_in,
                              void* d_out, int out_size) {
    const float* x        = (const float*)d_in[0];
    const float* edge_val = (const float*)d_in[1];
    const float* W1       = (const float*)d_in[2];
    const float* b1       = (const float*)d_in[3];
    const float* W2       = (const float*)d_in[4];
    const float* b2       = (const float*)d_in[5];
    const float* W3       = (const float*)d_in[6];
    const float* b3       = (const float*)d_in[7];
    const int*   esrc     = (const int*)d_in[8];
    const int*   edst     = (const int*)d_in[9];
    float* out = (float*)d_out;

    const int N = in_sizes[0] / 128;
    const int E = in_sizes[8];

    float *sup, *hA, *hB;
    cudaGetSymbolAddress((void**)&sup, g_sup);
    cudaGetSymbolAddress((void**)&hA, g_hA);
    cudaGetSymbolAddress((void**)&hB, g_hB);

    const int gemm_blocks = (N + 127) / 128;
    const int g64_blocks  = (N * 32 + 255) / 256;   // G=32 threads/node
    const int g16_blocks  = (N * 8 + 255) / 256;    // G=8 threads/node

    // Build + pad dst-buckets once; reused by all three SpMM gathers.
    zero_cnt_kernel<<<(N + 255) / 256, 256>>>(N);
    bucket_build_kernel<<<(E + 255) / 256, 256>>>(esrc, edst, edge_val, E);
    bucket_pad_kernel<<<(N + 255) / 256, 256>>>(N);

    // Layer 1: sup = x@W1 ; hA = gather(sup) + b1
    gemm_kernel<128, 64, false><<<gemm_blocks, 256>>>(x, W1, sup, N);
    gather_spmm_kernel<64><<<g64_blocks, 256>>>(sup, b1, hA, N);

    // Layer 2: sup = relu(hA)@W2 ; hB = gather(sup) + b2
    gemm_kernel<64, 64, true><<<gemm_blocks, 256>>>(hA, W2, sup, N);
    gather_spmm_kernel<64><<<g64_blocks, 256>>>(sup, b2, hB, N);

    // Layer 3: sup = relu(hB)@W3 ; out = gather(sup) + b3
    gemm_kernel<64, 16, true><<<gemm_blocks, 256>>>(hB, W3, sup, N);
    gather_spmm_kernel<16><<<g16_blocks, 256>>>(sup, b3, out, N);
}